// round 5
// baseline (speedup 1.0000x reference)
#include <cuda_runtime.h>
#include <cstdint>

// Problem constants (fixed shapes per reference)
#define N_NODES 100000
#define F_IN    256
#define H_DIM   128
#define D_DIM   64

// ---------------- scratch (device globals; no allocation allowed) -------------
__device__ __align__(16) float g_deg [N_NODES];              // degree incl. self-loop
__device__ __align__(16) float g_h1  [N_NODES * H_DIM];      // x @ W1
__device__ __align__(16) float g_agg1[N_NODES * H_DIM];      // aggregated layer-1 pre-act
__device__ __align__(16) float g_h2  [N_NODES * H_DIM];      // relu(agg1 + b1)
__device__ __align__(16) float g_agg2[N_NODES * H_DIM];      // aggregated h2
__device__ __align__(16) float g_Wc  [H_DIM * 128];          // [Wmu | Wvar] row-major [128,128]
__device__ __align__(16) float g_bc  [128];                  // [bmu | bvar]

// ---------------- degree ---------------------------------------------------------
__global__ void deg_init_kernel() {
    int i = blockIdx.x * blockDim.x + threadIdx.x;
    if (i < N_NODES) g_deg[i] = 1.0f;          // self-loop contributes 1
}

__global__ void deg_count_kernel(const int* __restrict__ dst, int E) {
    int i = blockIdx.x * blockDim.x + threadIdx.x;
    if (i < E) atomicAdd(&g_deg[dst[i]], 1.0f);
}

// ---------------- pack [Wmu|Wvar] and [bmu|bvar] -------------------------------
__global__ void pack_w_kernel(const float* __restrict__ Wmu, const float* __restrict__ Wvar,
                              const float* __restrict__ bmu, const float* __restrict__ bvar) {
    int i = blockIdx.x * blockDim.x + threadIdx.x;   // 0 .. 128*128-1
    if (i < H_DIM * 128) {
        int k = i >> 7, c = i & 127;
        g_Wc[i] = (c < D_DIM) ? Wmu[k * D_DIM + c] : Wvar[k * D_DIM + (c - D_DIM)];
    }
    if (i < 128) g_bc[i] = (i < D_DIM) ? bmu[i] : bvar[i - D_DIM];
}

// ---------------- SGEMM: C[M,128] = A[M,K] @ B[K,128] ---------------------------
// BM=128, BN=128, BK=16, 256 threads, 8x8 micro-tile (split 4+4 layout ->
// conflict-free LDS.128), double-buffered smem.
// Thread (tx,ty) owns rows {ty*4..+3, 64+ty*4..+3} x cols {tx*4..+3, 64+tx*4..+3}.
// MODE 0: A = x,  B = W1; epilogue writes g_h1 AND g_agg1 = h1 / deg (fused self-loop)
// MODE 1: A = g_agg2, B = g_Wc; epilogue adds g_bc, split-writes mu/sigma to d_out
template <int MODE>
__global__ void __launch_bounds__(256)
sgemm_kernel(const float* __restrict__ Ap, const float* __restrict__ Bp,
             float* __restrict__ outMu, float* __restrict__ outSig,
             int M, int K) {
    __shared__ float As[2][16][132];   // [buf][k][m] padded, rows 16B-aligned
    __shared__ float Bs[2][16][128];   // [buf][k][n]

    const float* A = (MODE == 0) ? Ap : g_agg2;
    const float* B = (MODE == 0) ? Bp : g_Wc;

    const int tid  = threadIdx.x;
    const int row0 = blockIdx.x * 128;
    const int tx   = tid & 15;        // column group
    const int ty   = tid >> 4;        // row group

    float acc[8][8];
#pragma unroll
    for (int i = 0; i < 8; i++)
#pragma unroll
        for (int j = 0; j < 8; j++) acc[i][j] = 0.0f;

    // tile loader: A tile 128x16 (transposed into As), B tile 16x128
    auto load_tile = [&](int k0, int buf) {
#pragma unroll
        for (int i = 0; i < 2; i++) {
            int lin = tid + i * 256;                 // 0..511
            int r = lin >> 2, q = (lin & 3) * 4;     // A: row r, k-quad q
            int gr = row0 + r;
            float4 va = make_float4(0.f, 0.f, 0.f, 0.f);
            if (gr < M) va = *(const float4*)&A[(size_t)gr * K + k0 + q];
            As[buf][q + 0][r] = va.x;
            As[buf][q + 1][r] = va.y;
            As[buf][q + 2][r] = va.z;
            As[buf][q + 3][r] = va.w;
            int bk = lin >> 5, bn = (lin & 31) * 4;  // B: k row, n-quad
            *(float4*)&Bs[buf][bk][bn] = *(const float4*)&B[(size_t)(k0 + bk) * 128 + bn];
        }
    };

    const int steps = K / 16;
    load_tile(0, 0);
    __syncthreads();

    for (int s = 0; s < steps; s++) {
        if (s + 1 < steps) load_tile((s + 1) * 16, (s + 1) & 1);
        const int cb = s & 1;
#pragma unroll
        for (int kk = 0; kk < 16; kk++) {
            float4 a0 = *(const float4*)&As[cb][kk][ty * 4];        // rows ty*4..+3
            float4 a1 = *(const float4*)&As[cb][kk][64 + ty * 4];   // rows 64+ty*4..+3
            float4 b0 = *(const float4*)&Bs[cb][kk][tx * 4];        // cols tx*4..+3
            float4 b1 = *(const float4*)&Bs[cb][kk][64 + tx * 4];   // cols 64+tx*4..+3
            float a[8] = {a0.x, a0.y, a0.z, a0.w, a1.x, a1.y, a1.z, a1.w};
            float b[8] = {b0.x, b0.y, b0.z, b0.w, b1.x, b1.y, b1.z, b1.w};
#pragma unroll
            for (int i = 0; i < 8; i++)
#pragma unroll
                for (int j = 0; j < 8; j++)
                    acc[i][j] = fmaf(a[i], b[j], acc[i][j]);
        }
        __syncthreads();
    }

    if (MODE == 1) {
        float bc0[4], bc1[4];
#pragma unroll
        for (int j = 0; j < 4; j++) {
            bc0[j] = g_bc[tx * 4 + j];        // mu half  (cols 0..63)
            bc1[j] = g_bc[64 + tx * 4 + j];   // sig half (cols 64..127)
        }
#pragma unroll
        for (int i = 0; i < 8; i++) {
            int rr = (i < 4) ? (ty * 4 + i) : (64 + ty * 4 + i - 4);
            int gr = row0 + rr;
            if (gr >= M) continue;
            float4 v0 = make_float4(acc[i][0] + bc0[0], acc[i][1] + bc0[1],
                                    acc[i][2] + bc0[2], acc[i][3] + bc0[3]);
            float4 v1 = make_float4(acc[i][4] + bc1[0], acc[i][5] + bc1[1],
                                    acc[i][6] + bc1[2], acc[i][7] + bc1[3]);
            *(float4*)&outMu [(size_t)gr * D_DIM + tx * 4] = v0;
            *(float4*)&outSig[(size_t)gr * D_DIM + tx * 4] = v1;
        }
    } else {
#pragma unroll
        for (int i = 0; i < 8; i++) {
            int rr = (i < 4) ? (ty * 4 + i) : (64 + ty * 4 + i - 4);
            int gr = row0 + rr;
            if (gr >= M) continue;
            float d2 = 1.0f / g_deg[gr];
            float4 v0 = make_float4(acc[i][0], acc[i][1], acc[i][2], acc[i][3]);
            float4 v1 = make_float4(acc[i][4], acc[i][5], acc[i][6], acc[i][7]);
            *(float4*)&g_h1[(size_t)gr * 128 + tx * 4]      = v0;
            *(float4*)&g_h1[(size_t)gr * 128 + 64 + tx * 4] = v1;
            float4 w0 = make_float4(v0.x * d2, v0.y * d2, v0.z * d2, v0.w * d2);
            float4 w1 = make_float4(v1.x * d2, v1.y * d2, v1.z * d2, v1.w * d2);
            *(float4*)&g_agg1[(size_t)gr * 128 + tx * 4]      = w0;
            *(float4*)&g_agg1[(size_t)gr * 128 + 64 + tx * 4] = w1;
        }
    }
}

// ---------------- edge scatter: agg[dst] += h[src] * rsqrt(deg_s*deg_d) ----------
// 8 edges per warp: lanes 0-7 load src idx + deg, lanes 8-15 load dst idx + deg;
// distributed via shfl; 8 independent 16B gathers in flight per lane (MLP=8).
template <int LAYER>   // 0: h1->agg1, 1: h2->agg2
__global__ void __launch_bounds__(256)
scatter_kernel(const int* __restrict__ src, const int* __restrict__ dst, int E) {
    int warp = (blockIdx.x * blockDim.x + threadIdx.x) >> 5;
    int lane = threadIdx.x & 31;
    int e0 = warp * 8;
    if (e0 >= E) return;

    int   iv = 0;
    float dv = 0.0f;
    if (lane < 8) {
        int e = min(e0 + lane, E - 1);
        iv = src[e];
        dv = g_deg[iv];
    } else if (lane < 16) {
        int e = min(e0 + lane - 8, E - 1);
        iv = dst[e];
        dv = g_deg[iv];
    }

    const float* h = (LAYER == 0) ? g_h1 : g_h2;
    float* agg     = (LAYER == 0) ? g_agg1 : g_agg2;

    int   ss[8], dd[8];
    float nn[8];
#pragma unroll
    for (int j = 0; j < 8; j++) {
        ss[j] = __shfl_sync(0xffffffffu, iv, j);
        dd[j] = __shfl_sync(0xffffffffu, iv, 8 + j);
        float ds = __shfl_sync(0xffffffffu, dv, j);
        float dt = __shfl_sync(0xffffffffu, dv, 8 + j);
        nn[j] = rsqrtf(ds * dt);
    }

    float4 v[8];
#pragma unroll
    for (int j = 0; j < 8; j++)
        v[j] = ((const float4*)(h + (size_t)ss[j] * 128))[lane];

#pragma unroll
    for (int j = 0; j < 8; j++) {
        if (e0 + j < E) {
            float n = nn[j];
            float* out = agg + (size_t)dd[j] * 128 + lane * 4;
            asm volatile("red.global.add.v4.f32 [%0], {%1,%2,%3,%4};"
                         :: "l"(out), "f"(v[j].x * n), "f"(v[j].y * n),
                            "f"(v[j].z * n), "f"(v[j].w * n)
                         : "memory");
        }
    }
}

// ---------------- h2 = relu(agg1 + b1); agg2 = h2 / deg --------------------------
__global__ void relu_init_kernel(const float* __restrict__ b1) {
    int idx = blockIdx.x * blockDim.x + threadIdx.x;   // over N_NODES*32 float4s
    if (idx >= N_NODES * 32) return;
    int node = idx >> 5, c4 = idx & 31;
    float4 v = ((const float4*)(g_agg1 + (size_t)node * 128))[c4];
    float4 b = ((const float4*)b1)[c4];
    v.x = fmaxf(v.x + b.x, 0.0f);
    v.y = fmaxf(v.y + b.y, 0.0f);
    v.z = fmaxf(v.z + b.z, 0.0f);
    v.w = fmaxf(v.w + b.w, 0.0f);
    ((float4*)(g_h2 + (size_t)node * 128))[c4] = v;
    float d2 = 1.0f / g_deg[node];
    v.x *= d2; v.y *= d2; v.z *= d2; v.w *= d2;
    ((float4*)(g_agg2 + (size_t)node * 128))[c4] = v;
}

// --------------------------------------------------------------------------------
extern "C" void kernel_launch(void* const* d_in, const int* in_sizes, int n_in,
                              void* d_out, int out_size) {
    const float* x    = (const float*)d_in[0];
    const int*   ei   = (const int*)d_in[1];     // edge_index: int32
    const float* W1   = (const float*)d_in[2];
    const float* b1   = (const float*)d_in[3];
    const float* Wmu  = (const float*)d_in[4];
    const float* bmu  = (const float*)d_in[5];
    const float* Wvar = (const float*)d_in[6];
    const float* bvar = (const float*)d_in[7];

    const int E = in_sizes[1] / 2;
    const int* src = ei;
    const int* dst = ei + E;

    float* outMu  = (float*)d_out;
    float* outSig = (float*)d_out + (size_t)N_NODES * D_DIM;

    const int scatterWarps  = (E + 7) / 8;
    const int scatterBlocks = (scatterWarps * 32 + 255) / 256;

    // 1-2: degree
    deg_init_kernel <<<(N_NODES + 255) / 256, 256>>>();
    deg_count_kernel<<<(E + 255) / 256, 256>>>(dst, E);

    // 3: layer-1 GEMM with fused self-loop init (h1, agg1 = h1/deg)
    sgemm_kernel<0><<<(N_NODES + 127) / 128, 256>>>(x, W1, nullptr, nullptr, N_NODES, F_IN);

    // 4: layer-1 edge scatter (ncu capture slot)
    scatter_kernel<0><<<scatterBlocks, 256>>>(src, dst, E);

    // 5: relu + layer-2 self-loop init (h2, agg2 = h2/deg)
    relu_init_kernel<<<(N_NODES * 32 + 255) / 256, 256>>>(b1);

    // 6: layer-2 edge scatter
    scatter_kernel<1><<<scatterBlocks, 256>>>(src, dst, E);

    // 7: pack fused projection weights
    pack_w_kernel<<<(H_DIM * 128 + 255) / 256, 256>>>(Wmu, Wvar, bmu, bvar);

    // 8: fused mu/sigma projection into d_out
    sgemm_kernel<1><<<(N_NODES + 127) / 128, 256>>>(nullptr, nullptr, outMu, outSig,
                                                    N_NODES, H_DIM);
}

// round 6
// speedup vs baseline: 1.2678x; 1.2678x over previous
#include <cuda_runtime.h>
#include <cstdint>

// Problem constants (fixed shapes per reference)
#define N_NODES 100000
#define F_IN    256
#define H_DIM   128
#define D_DIM   64
#define MAX_E   1700000

// ---------------- scratch (device globals; no allocation allowed) -------------
__device__ __align__(16) int   g_cnt [N_NODES];              // per-dst edge count / fill cursor
__device__ __align__(16) int   g_row [N_NODES + 1];          // CSR row offsets
__device__ __align__(16) float g_dinv[N_NODES];              // rsqrt(deg) incl self-loop
__device__ __align__(16) int2  g_csr [MAX_E];                // {src, norm-as-int-bits}
__device__ __align__(16) float g_h1  [N_NODES * H_DIM];      // x @ W1
__device__ __align__(16) float g_agg1[N_NODES * H_DIM];      // aggregated layer-1 pre-act
__device__ __align__(16) float g_h2  [N_NODES * H_DIM];      // relu(agg1 + b1)
__device__ __align__(16) float g_agg2[N_NODES * H_DIM];      // aggregated h2
__device__ __align__(16) float g_Wc  [H_DIM * 128];          // [Wmu | Wvar] row-major [128,128]
__device__ __align__(16) float g_bc  [128];                  // [bmu | bvar]

// ---------------- CSR build ------------------------------------------------------
__global__ void zero_cnt_kernel() {
    int i = blockIdx.x * blockDim.x + threadIdx.x;
    if (i < N_NODES) g_cnt[i] = 0;
}

__global__ void count_kernel(const int* __restrict__ dst, int E) {
    int i = blockIdx.x * blockDim.x + threadIdx.x;
    if (i < E) atomicAdd(&g_cnt[dst[i]], 1);
}

// Single-block exclusive scan over g_cnt -> g_row, plus dinv, plus cnt reset.
__global__ void scan_kernel() {            // <<<1, 1024>>>
    __shared__ int warp_sums[32];
    __shared__ int s_carry;
    const int tid = threadIdx.x, lane = tid & 31, wid = tid >> 5;
    if (tid == 0) s_carry = 0;
    __syncthreads();
    for (int base = 0; base < N_NODES; base += 1024) {
        int i = base + tid;
        int v = (i < N_NODES) ? g_cnt[i] : 0;
        if (i < N_NODES) {
            g_dinv[i] = rsqrtf((float)v + 1.0f);   // +1 self-loop
            g_cnt[i] = 0;                           // reset as fill cursor
        }
        // warp inclusive scan
        int x = v;
#pragma unroll
        for (int off = 1; off < 32; off <<= 1) {
            int t = __shfl_up_sync(0xffffffffu, x, off);
            if (lane >= off) x += t;
        }
        if (lane == 31) warp_sums[wid] = x;
        __syncthreads();
        if (wid == 0) {
            int y = warp_sums[lane];
#pragma unroll
            for (int off = 1; off < 32; off <<= 1) {
                int t = __shfl_up_sync(0xffffffffu, y, off);
                if (lane >= off) y += t;
            }
            warp_sums[lane] = y;                    // inclusive warp prefix
        }
        __syncthreads();
        int warp_off = (wid == 0) ? 0 : warp_sums[wid - 1];
        if (i < N_NODES) g_row[i] = s_carry + warp_off + x - v;   // exclusive
        __syncthreads();                            // all reads of s_carry done
        if (tid == 1023) s_carry += warp_sums[31];
        __syncthreads();
    }
    if (threadIdx.x == 0) g_row[N_NODES] = s_carry;
}

__global__ void fill_kernel(const int* __restrict__ src, const int* __restrict__ dst, int E) {
    int e = blockIdx.x * blockDim.x + threadIdx.x;
    if (e >= E) return;
    int s = src[e], d = dst[e];
    int pos = g_row[d] + atomicAdd(&g_cnt[d], 1);
    g_csr[pos] = make_int2(s, __float_as_int(g_dinv[s] * g_dinv[d]));
}

// ---------------- pack [Wmu|Wvar] and [bmu|bvar] -------------------------------
__global__ void pack_w_kernel(const float* __restrict__ Wmu, const float* __restrict__ Wvar,
                              const float* __restrict__ bmu, const float* __restrict__ bvar) {
    int i = blockIdx.x * blockDim.x + threadIdx.x;   // 0 .. 128*128-1
    if (i < H_DIM * 128) {
        int k = i >> 7, c = i & 127;
        g_Wc[i] = (c < D_DIM) ? Wmu[k * D_DIM + c] : Wvar[k * D_DIM + (c - D_DIM)];
    }
    if (i < 128) g_bc[i] = (i < D_DIM) ? bmu[i] : bvar[i - D_DIM];
}

// ---------------- SGEMM: C[M,128] = A[M,K] @ B[K,128] ---------------------------
// BM=128, BN=128, BK=16, 256 threads, 8x8 micro-tile (split 4+4 layout ->
// conflict-free LDS.128), double-buffered smem.
// MODE 0: A = x,  B = W1; epilogue writes g_h1 only
// MODE 1: A = g_agg2, B = g_Wc; epilogue adds g_bc, split-writes mu/sigma to d_out
template <int MODE>
__global__ void __launch_bounds__(256)
sgemm_kernel(const float* __restrict__ Ap, const float* __restrict__ Bp,
             float* __restrict__ outMu, float* __restrict__ outSig,
             int M, int K) {
    __shared__ float As[2][16][132];   // [buf][k][m] padded, rows 16B-aligned
    __shared__ float Bs[2][16][128];   // [buf][k][n]

    const float* A = (MODE == 0) ? Ap : g_agg2;
    const float* B = (MODE == 0) ? Bp : g_Wc;

    const int tid  = threadIdx.x;
    const int row0 = blockIdx.x * 128;
    const int tx   = tid & 15;        // column group
    const int ty   = tid >> 4;        // row group

    float acc[8][8];
#pragma unroll
    for (int i = 0; i < 8; i++)
#pragma unroll
        for (int j = 0; j < 8; j++) acc[i][j] = 0.0f;

    auto load_tile = [&](int k0, int buf) {
#pragma unroll
        for (int i = 0; i < 2; i++) {
            int lin = tid + i * 256;                 // 0..511
            int r = lin >> 2, q = (lin & 3) * 4;     // A: row r, k-quad q
            int gr = row0 + r;
            float4 va = make_float4(0.f, 0.f, 0.f, 0.f);
            if (gr < M) va = *(const float4*)&A[(size_t)gr * K + k0 + q];
            As[buf][q + 0][r] = va.x;
            As[buf][q + 1][r] = va.y;
            As[buf][q + 2][r] = va.z;
            As[buf][q + 3][r] = va.w;
            int bk = lin >> 5, bn = (lin & 31) * 4;  // B: k row, n-quad
            *(float4*)&Bs[buf][bk][bn] = *(const float4*)&B[(size_t)(k0 + bk) * 128 + bn];
        }
    };

    const int steps = K / 16;
    load_tile(0, 0);
    __syncthreads();

    for (int s = 0; s < steps; s++) {
        if (s + 1 < steps) load_tile((s + 1) * 16, (s + 1) & 1);
        const int cb = s & 1;
#pragma unroll
        for (int kk = 0; kk < 16; kk++) {
            float4 a0 = *(const float4*)&As[cb][kk][ty * 4];
            float4 a1 = *(const float4*)&As[cb][kk][64 + ty * 4];
            float4 b0 = *(const float4*)&Bs[cb][kk][tx * 4];
            float4 b1 = *(const float4*)&Bs[cb][kk][64 + tx * 4];
            float a[8] = {a0.x, a0.y, a0.z, a0.w, a1.x, a1.y, a1.z, a1.w};
            float b[8] = {b0.x, b0.y, b0.z, b0.w, b1.x, b1.y, b1.z, b1.w};
#pragma unroll
            for (int i = 0; i < 8; i++)
#pragma unroll
                for (int j = 0; j < 8; j++)
                    acc[i][j] = fmaf(a[i], b[j], acc[i][j]);
        }
        __syncthreads();
    }

    if (MODE == 1) {
        float bc0[4], bc1[4];
#pragma unroll
        for (int j = 0; j < 4; j++) {
            bc0[j] = g_bc[tx * 4 + j];        // mu half  (cols 0..63)
            bc1[j] = g_bc[64 + tx * 4 + j];   // sig half (cols 64..127)
        }
#pragma unroll
        for (int i = 0; i < 8; i++) {
            int rr = (i < 4) ? (ty * 4 + i) : (64 + ty * 4 + i - 4);
            int gr = row0 + rr;
            if (gr >= M) continue;
            float4 v0 = make_float4(acc[i][0] + bc0[0], acc[i][1] + bc0[1],
                                    acc[i][2] + bc0[2], acc[i][3] + bc0[3]);
            float4 v1 = make_float4(acc[i][4] + bc1[0], acc[i][5] + bc1[1],
                                    acc[i][6] + bc1[2], acc[i][7] + bc1[3]);
            *(float4*)&outMu [(size_t)gr * D_DIM + tx * 4] = v0;
            *(float4*)&outSig[(size_t)gr * D_DIM + tx * 4] = v1;
        }
    } else {
#pragma unroll
        for (int i = 0; i < 8; i++) {
            int rr = (i < 4) ? (ty * 4 + i) : (64 + ty * 4 + i - 4);
            int gr = row0 + rr;
            if (gr >= M) continue;
            *(float4*)&g_h1[(size_t)gr * 128 + tx * 4] =
                make_float4(acc[i][0], acc[i][1], acc[i][2], acc[i][3]);
            *(float4*)&g_h1[(size_t)gr * 128 + 64 + tx * 4] =
                make_float4(acc[i][4], acc[i][5], acc[i][6], acc[i][7]);
        }
    }
}

// ---------------- CSR gather-aggregate: agg[n] = h[n]*dinv^2 + sum h[s]*norm ----
// One warp per node; neighbor entries loaded coalesced (int2), broadcast via shfl;
// 4 independent gathers in flight per lane. Row written exactly once (no atomics).
template <int LAYER>   // 0: h1->agg1, 1: h2->agg2
__global__ void __launch_bounds__(256)
aggregate_kernel() {
    int n    = (blockIdx.x * 256 + threadIdx.x) >> 5;
    int lane = threadIdx.x & 31;
    if (n >= N_NODES) return;

    const float* h = (LAYER == 0) ? g_h1 : g_h2;
    float* agg     = (LAYER == 0) ? g_agg1 : g_agg2;

    float di = g_dinv[n];
    float d2 = di * di;
    float4 acc = ((const float4*)(h + (size_t)n * 128))[lane];
    acc.x *= d2; acc.y *= d2; acc.z *= d2; acc.w *= d2;

    int r0 = g_row[n], r1 = g_row[n + 1];
    for (int base = r0; base < r1; base += 32) {
        int rem = min(r1 - base, 32);
        int2 ent = make_int2(0, 0);
        if (lane < rem) ent = g_csr[base + lane];

        int k = 0;
        for (; k + 4 <= rem; k += 4) {
            int   s0 = __shfl_sync(0xffffffffu, ent.x, k + 0);
            int   s1 = __shfl_sync(0xffffffffu, ent.x, k + 1);
            int   s2 = __shfl_sync(0xffffffffu, ent.x, k + 2);
            int   s3 = __shfl_sync(0xffffffffu, ent.x, k + 3);
            float w0 = __int_as_float(__shfl_sync(0xffffffffu, ent.y, k + 0));
            float w1 = __int_as_float(__shfl_sync(0xffffffffu, ent.y, k + 1));
            float w2 = __int_as_float(__shfl_sync(0xffffffffu, ent.y, k + 2));
            float w3 = __int_as_float(__shfl_sync(0xffffffffu, ent.y, k + 3));
            float4 v0 = ((const float4*)(h + (size_t)s0 * 128))[lane];
            float4 v1 = ((const float4*)(h + (size_t)s1 * 128))[lane];
            float4 v2 = ((const float4*)(h + (size_t)s2 * 128))[lane];
            float4 v3 = ((const float4*)(h + (size_t)s3 * 128))[lane];
            acc.x = fmaf(v0.x, w0, acc.x); acc.y = fmaf(v0.y, w0, acc.y);
            acc.z = fmaf(v0.z, w0, acc.z); acc.w = fmaf(v0.w, w0, acc.w);
            acc.x = fmaf(v1.x, w1, acc.x); acc.y = fmaf(v1.y, w1, acc.y);
            acc.z = fmaf(v1.z, w1, acc.z); acc.w = fmaf(v1.w, w1, acc.w);
            acc.x = fmaf(v2.x, w2, acc.x); acc.y = fmaf(v2.y, w2, acc.y);
            acc.z = fmaf(v2.z, w2, acc.z); acc.w = fmaf(v2.w, w2, acc.w);
            acc.x = fmaf(v3.x, w3, acc.x); acc.y = fmaf(v3.y, w3, acc.y);
            acc.z = fmaf(v3.z, w3, acc.z); acc.w = fmaf(v3.w, w3, acc.w);
        }
        for (; k < rem; k++) {
            int   s = __shfl_sync(0xffffffffu, ent.x, k);
            float w = __int_as_float(__shfl_sync(0xffffffffu, ent.y, k));
            float4 v = ((const float4*)(h + (size_t)s * 128))[lane];
            acc.x = fmaf(v.x, w, acc.x); acc.y = fmaf(v.y, w, acc.y);
            acc.z = fmaf(v.z, w, acc.z); acc.w = fmaf(v.w, w, acc.w);
        }
    }
    ((float4*)(agg + (size_t)n * 128))[lane] = acc;
}

// ---------------- h2 = relu(agg1 + b1) -------------------------------------------
__global__ void relu_kernel(const float* __restrict__ b1) {
    int idx = blockIdx.x * blockDim.x + threadIdx.x;   // over N_NODES*32 float4s
    if (idx >= N_NODES * 32) return;
    int node = idx >> 5, c4 = idx & 31;
    float4 v = ((const float4*)(g_agg1 + (size_t)node * 128))[c4];
    float4 b = ((const float4*)b1)[c4];
    v.x = fmaxf(v.x + b.x, 0.0f);
    v.y = fmaxf(v.y + b.y, 0.0f);
    v.z = fmaxf(v.z + b.z, 0.0f);
    v.w = fmaxf(v.w + b.w, 0.0f);
    ((float4*)(g_h2 + (size_t)node * 128))[c4] = v;
}

// --------------------------------------------------------------------------------
extern "C" void kernel_launch(void* const* d_in, const int* in_sizes, int n_in,
                              void* d_out, int out_size) {
    const float* x    = (const float*)d_in[0];
    const int*   ei   = (const int*)d_in[1];     // edge_index: int32
    const float* W1   = (const float*)d_in[2];
    const float* b1   = (const float*)d_in[3];
    const float* Wmu  = (const float*)d_in[4];
    const float* bmu  = (const float*)d_in[5];
    const float* Wvar = (const float*)d_in[6];
    const float* bvar = (const float*)d_in[7];

    const int E = in_sizes[1] / 2;
    const int* src = ei;
    const int* dst = ei + E;

    float* outMu  = (float*)d_out;
    float* outSig = (float*)d_out + (size_t)N_NODES * D_DIM;

    const int aggBlocks = (N_NODES * 32 + 255) / 256;   // one warp per node

    // 1-4: CSR build (fill lands in ncu capture slot #4)
    zero_cnt_kernel<<<(N_NODES + 255) / 256, 256>>>();
    count_kernel  <<<(E + 255) / 256, 256>>>(dst, E);
    scan_kernel   <<<1, 1024>>>();
    fill_kernel   <<<(E + 255) / 256, 256>>>(src, dst, E);

    // 5: layer-1 GEMM (h1)
    sgemm_kernel<0><<<(N_NODES + 127) / 128, 256>>>(x, W1, nullptr, nullptr, N_NODES, F_IN);

    // 6: layer-1 aggregate (agg1, self-loop fused)
    aggregate_kernel<0><<<aggBlocks, 256>>>();

    // 7: relu (h2)
    relu_kernel<<<(N_NODES * 32 + 255) / 256, 256>>>(b1);

    // 8: layer-2 aggregate (agg2)
    aggregate_kernel<1><<<aggBlocks, 256>>>();

    // 9: pack fused projection weights
    pack_w_kernel<<<(H_DIM * 128 + 255) / 256, 256>>>(Wmu, Wvar, bmu, bvar);

    // 10: fused mu/sigma projection into d_out
    sgemm_kernel<1><<<(N_NODES + 127) / 128, 256>>>(nullptr, nullptr, outMu, outSig,
                                                    N_NODES, H_DIM);
}

// round 7
// speedup vs baseline: 1.3747x; 1.0844x over previous
#include <cuda_runtime.h>
#include <cstdint>

// Problem constants (fixed shapes per reference)
#define N_NODES 100000
#define F_IN    256
#define H_DIM   128
#define D_DIM   64
#define MAX_E   1700000

// ---------------- scratch (device globals; no allocation allowed) -------------
__device__ __align__(16) int   g_cnt [N_NODES];              // per-dst edge count / fill cursor
__device__ __align__(16) int   g_row [N_NODES + 1];          // CSR row offsets
__device__ __align__(16) float g_dinv[N_NODES];              // rsqrt(deg) incl self-loop
__device__ __align__(16) int2  g_csr [MAX_E];                // {src, norm-as-int-bits}
__device__ __align__(16) float g_h1  [N_NODES * H_DIM];      // x @ W1
__device__ __align__(16) float g_h2  [N_NODES * H_DIM];      // relu(agg1 + b1)
__device__ __align__(16) float g_agg2[N_NODES * H_DIM];      // aggregated h2
__device__ __align__(16) float g_Wc  [H_DIM * 128];          // [Wmu | Wvar] row-major [128,128]
__device__ __align__(16) float g_bc  [128];                  // [bmu | bvar]

// ---------------- CSR build ------------------------------------------------------
__global__ void zero_cnt_kernel() {
    int i = blockIdx.x * blockDim.x + threadIdx.x;
    if (i < N_NODES) g_cnt[i] = 0;
}

__global__ void count_kernel(const int* __restrict__ dst, int E) {
    int i = blockIdx.x * blockDim.x + threadIdx.x;
    if (i < E) atomicAdd(&g_cnt[dst[i]], 1);
}

// Single-block exclusive scan over g_cnt -> g_row, plus dinv, plus cnt reset.
__global__ void scan_kernel() {            // <<<1, 1024>>>
    __shared__ int warp_sums[32];
    __shared__ int s_carry;
    const int tid = threadIdx.x, lane = tid & 31, wid = tid >> 5;
    if (tid == 0) s_carry = 0;
    __syncthreads();
    for (int base = 0; base < N_NODES; base += 1024) {
        int i = base + tid;
        int v = (i < N_NODES) ? g_cnt[i] : 0;
        if (i < N_NODES) {
            g_dinv[i] = rsqrtf((float)v + 1.0f);   // +1 self-loop
            g_cnt[i] = 0;                           // reset as fill cursor
        }
        int x = v;
#pragma unroll
        for (int off = 1; off < 32; off <<= 1) {
            int t = __shfl_up_sync(0xffffffffu, x, off);
            if (lane >= off) x += t;
        }
        if (lane == 31) warp_sums[wid] = x;
        __syncthreads();
        if (wid == 0) {
            int y = warp_sums[lane];
#pragma unroll
            for (int off = 1; off < 32; off <<= 1) {
                int t = __shfl_up_sync(0xffffffffu, y, off);
                if (lane >= off) y += t;
            }
            warp_sums[lane] = y;
        }
        __syncthreads();
        int warp_off = (wid == 0) ? 0 : warp_sums[wid - 1];
        if (i < N_NODES) g_row[i] = s_carry + warp_off + x - v;   // exclusive
        __syncthreads();
        if (tid == 1023) s_carry += warp_sums[31];
        __syncthreads();
    }
    if (threadIdx.x == 0) g_row[N_NODES] = s_carry;
}

__global__ void fill_kernel(const int* __restrict__ src, const int* __restrict__ dst, int E) {
    int e = blockIdx.x * blockDim.x + threadIdx.x;
    if (e >= E) return;
    int s = src[e], d = dst[e];
    int pos = g_row[d] + atomicAdd(&g_cnt[d], 1);
    g_csr[pos] = make_int2(s, __float_as_int(g_dinv[s] * g_dinv[d]));
}

// ---------------- pack [Wmu|Wvar] and [bmu|bvar] -------------------------------
__global__ void pack_w_kernel(const float* __restrict__ Wmu, const float* __restrict__ Wvar,
                              const float* __restrict__ bmu, const float* __restrict__ bvar) {
    int i = blockIdx.x * blockDim.x + threadIdx.x;   // 0 .. 128*128-1
    if (i < H_DIM * 128) {
        int k = i >> 7, c = i & 127;
        g_Wc[i] = (c < D_DIM) ? Wmu[k * D_DIM + c] : Wvar[k * D_DIM + (c - D_DIM)];
    }
    if (i < 128) g_bc[i] = (i < D_DIM) ? bmu[i] : bvar[i - D_DIM];
}

// ---------------- tf32 helpers ---------------------------------------------------
__device__ __forceinline__ uint32_t f2tf32(float f) {
    uint32_t u;
    asm("cvt.rna.tf32.f32 %0, %1;" : "=r"(u) : "f"(f));
    return u;
}

__device__ __forceinline__ void mma_tf32(float* d, const uint32_t* a, const uint32_t* b) {
    asm volatile(
        "mma.sync.aligned.m16n8k8.row.col.f32.tf32.tf32.f32 "
        "{%0,%1,%2,%3}, {%4,%5,%6,%7}, {%8,%9}, {%0,%1,%2,%3};"
        : "+f"(d[0]), "+f"(d[1]), "+f"(d[2]), "+f"(d[3])
        : "r"(a[0]), "r"(a[1]), "r"(a[2]), "r"(a[3]), "r"(b[0]), "r"(b[1]));
}

// ---------------- 3xTF32 tensor-core GEMM: C[M,128] = A[M,K] @ B[K,128] ----------
// Block 128x128, 256 threads = 8 warps as 2(m) x 4(n); warp tile 64x32
// = 4 m-tiles (m16) x 4 n-tiles (n8). BK=8 double-buffered. A/B split into
// tf32 hi/lo at staging; D = Ah*Bh + Ah*Bl + Al*Bh (3xTF32, ~fp32 accuracy).
// MODE 0: A = x, B = W1 -> g_h1. MODE 1: A = g_agg2, B = g_Wc, +bias -> mu|sigma.
template <int MODE>
__global__ void __launch_bounds__(256)
tgemm_kernel(const float* __restrict__ Ap, const float* __restrict__ Bp,
             float* __restrict__ outMu, float* __restrict__ outSig,
             int M, int K) {
    __shared__ __align__(16) uint32_t Ah[2][8][136];
    __shared__ __align__(16) uint32_t Al[2][8][136];
    __shared__ __align__(16) uint32_t Bh[2][8][136];
    __shared__ __align__(16) uint32_t Bl[2][8][136];

    const float* A = (MODE == 0) ? Ap : g_agg2;
    const float* B = (MODE == 0) ? Bp : g_Wc;

    const int tid    = threadIdx.x;
    const int lane   = tid & 31;
    const int wid    = tid >> 5;
    const int warp_m = wid >> 2;      // 0..1 (64 rows each)
    const int warp_n = wid & 3;       // 0..3 (32 cols each)
    const int gid    = lane >> 2;     // 0..7
    const int tig    = lane & 3;      // 0..3
    const int row0   = blockIdx.x * 128;

    float acc[4][4][4];
#pragma unroll
    for (int mt = 0; mt < 4; mt++)
#pragma unroll
        for (int nt = 0; nt < 4; nt++)
#pragma unroll
            for (int r = 0; r < 4; r++) acc[mt][nt][r] = 0.0f;

    auto load_tile = [&](int k0, int buf) {
        // A: 128 rows x 8 k.  thread: r = tid>>1 (row), qq = (tid&1)*4 (k-quad)
        int r = tid >> 1, qq = (tid & 1) * 4;
        int gr = row0 + r;
        float4 va = make_float4(0.f, 0.f, 0.f, 0.f);
        if (gr < M) va = *(const float4*)&A[(size_t)gr * K + k0 + qq];
        float av[4] = {va.x, va.y, va.z, va.w};
#pragma unroll
        for (int j = 0; j < 4; j++) {
            uint32_t hi = f2tf32(av[j]);
            float lo = av[j] - __uint_as_float(hi);
            Ah[buf][qq + j][r] = hi;
            Al[buf][qq + j][r] = f2tf32(lo);
        }
        // B: 8 k x 128 n.  thread: bk = tid>>5 (k row), bn = (tid&31)*4
        int bk = tid >> 5, bn = (tid & 31) * 4;
        float4 vb = *(const float4*)&B[(size_t)(k0 + bk) * 128 + bn];
        float bv[4] = {vb.x, vb.y, vb.z, vb.w};
        uint32_t hb[4], lb[4];
#pragma unroll
        for (int j = 0; j < 4; j++) {
            hb[j] = f2tf32(bv[j]);
            float lo = bv[j] - __uint_as_float(hb[j]);
            lb[j] = f2tf32(lo);
        }
        *(uint4*)&Bh[buf][bk][bn] = make_uint4(hb[0], hb[1], hb[2], hb[3]);
        *(uint4*)&Bl[buf][bk][bn] = make_uint4(lb[0], lb[1], lb[2], lb[3]);
    };

    const int steps = K / 8;
    load_tile(0, 0);
    __syncthreads();

    for (int s = 0; s < steps; s++) {
        if (s + 1 < steps) load_tile((s + 1) * 8, (s + 1) & 1);
        const int cb = s & 1;

        uint32_t fah[4][4], fal[4][4], fbh[4][2], fbl[4][2];
#pragma unroll
        for (int mt = 0; mt < 4; mt++) {
            int m0 = warp_m * 64 + mt * 16;
            fah[mt][0] = Ah[cb][tig][m0 + gid];
            fah[mt][1] = Ah[cb][tig][m0 + 8 + gid];
            fah[mt][2] = Ah[cb][tig + 4][m0 + gid];
            fah[mt][3] = Ah[cb][tig + 4][m0 + 8 + gid];
            fal[mt][0] = Al[cb][tig][m0 + gid];
            fal[mt][1] = Al[cb][tig][m0 + 8 + gid];
            fal[mt][2] = Al[cb][tig + 4][m0 + gid];
            fal[mt][3] = Al[cb][tig + 4][m0 + 8 + gid];
        }
#pragma unroll
        for (int nt = 0; nt < 4; nt++) {
            int n0 = warp_n * 32 + nt * 8;
            fbh[nt][0] = Bh[cb][tig][n0 + gid];
            fbh[nt][1] = Bh[cb][tig + 4][n0 + gid];
            fbl[nt][0] = Bl[cb][tig][n0 + gid];
            fbl[nt][1] = Bl[cb][tig + 4][n0 + gid];
        }
#pragma unroll
        for (int mt = 0; mt < 4; mt++)
#pragma unroll
            for (int nt = 0; nt < 4; nt++) {
                mma_tf32(acc[mt][nt], fah[mt], fbh[nt]);
                mma_tf32(acc[mt][nt], fah[mt], fbl[nt]);
                mma_tf32(acc[mt][nt], fal[mt], fbh[nt]);
            }
        __syncthreads();
    }

    // Epilogue. c0,c1 -> row gid, cols 2tig,2tig+1; c2,c3 -> row gid+8.
#pragma unroll
    for (int mt = 0; mt < 4; mt++) {
#pragma unroll
        for (int nt = 0; nt < 4; nt++) {
            int col = warp_n * 32 + nt * 8 + 2 * tig;
            int ra  = row0 + warp_m * 64 + mt * 16 + gid;
            int rb  = ra + 8;
            if (MODE == 0) {
                if (ra < M) *(float2*)&g_h1[(size_t)ra * 128 + col] =
                    make_float2(acc[mt][nt][0], acc[mt][nt][1]);
                if (rb < M) *(float2*)&g_h1[(size_t)rb * 128 + col] =
                    make_float2(acc[mt][nt][2], acc[mt][nt][3]);
            } else {
                float b0 = g_bc[col], b1 = g_bc[col + 1];
                float* baseA;
                float* baseB;
                if (col < 64) {
                    baseA = outMu + (size_t)ra * D_DIM + col;
                    baseB = outMu + (size_t)rb * D_DIM + col;
                } else {
                    baseA = outSig + (size_t)ra * D_DIM + (col - 64);
                    baseB = outSig + (size_t)rb * D_DIM + (col - 64);
                }
                if (ra < M) *(float2*)baseA =
                    make_float2(acc[mt][nt][0] + b0, acc[mt][nt][1] + b1);
                if (rb < M) *(float2*)baseB =
                    make_float2(acc[mt][nt][2] + b0, acc[mt][nt][3] + b1);
            }
        }
    }
}

// ---------------- CSR gather-aggregate --------------------------------------------
// One warp per node; LAYER 0: reads g_h1, writes g_h2 = relu(agg + b1) (relu fused)
// LAYER 1: reads g_h2, writes g_agg2.
template <int LAYER>
__global__ void __launch_bounds__(256)
aggregate_kernel(const float* __restrict__ b1) {
    int n    = (blockIdx.x * 256 + threadIdx.x) >> 5;
    int lane = threadIdx.x & 31;
    if (n >= N_NODES) return;

    const float* h = (LAYER == 0) ? g_h1 : g_h2;

    float di = g_dinv[n];
    float d2 = di * di;
    float4 acc = ((const float4*)(h + (size_t)n * 128))[lane];
    acc.x *= d2; acc.y *= d2; acc.z *= d2; acc.w *= d2;

    int r0 = g_row[n], r1 = g_row[n + 1];
    for (int base = r0; base < r1; base += 32) {
        int rem = min(r1 - base, 32);
        int2 ent = make_int2(0, 0);
        if (lane < rem) ent = g_csr[base + lane];

        int k = 0;
        for (; k + 4 <= rem; k += 4) {
            int   s0 = __shfl_sync(0xffffffffu, ent.x, k + 0);
            int   s1 = __shfl_sync(0xffffffffu, ent.x, k + 1);
            int   s2 = __shfl_sync(0xffffffffu, ent.x, k + 2);
            int   s3 = __shfl_sync(0xffffffffu, ent.x, k + 3);
            float w0 = __int_as_float(__shfl_sync(0xffffffffu, ent.y, k + 0));
            float w1 = __int_as_float(__shfl_sync(0xffffffffu, ent.y, k + 1));
            float w2 = __int_as_float(__shfl_sync(0xffffffffu, ent.y, k + 2));
            float w3 = __int_as_float(__shfl_sync(0xffffffffu, ent.y, k + 3));
            float4 v0 = ((const float4*)(h + (size_t)s0 * 128))[lane];
            float4 v1 = ((const float4*)(h + (size_t)s1 * 128))[lane];
            float4 v2 = ((const float4*)(h + (size_t)s2 * 128))[lane];
            float4 v3 = ((const float4*)(h + (size_t)s3 * 128))[lane];
            acc.x = fmaf(v0.x, w0, acc.x); acc.y = fmaf(v0.y, w0, acc.y);
            acc.z = fmaf(v0.z, w0, acc.z); acc.w = fmaf(v0.w, w0, acc.w);
            acc.x = fmaf(v1.x, w1, acc.x); acc.y = fmaf(v1.y, w1, acc.y);
            acc.z = fmaf(v1.z, w1, acc.z); acc.w = fmaf(v1.w, w1, acc.w);
            acc.x = fmaf(v2.x, w2, acc.x); acc.y = fmaf(v2.y, w2, acc.y);
            acc.z = fmaf(v2.z, w2, acc.z); acc.w = fmaf(v2.w, w2, acc.w);
            acc.x = fmaf(v3.x, w3, acc.x); acc.y = fmaf(v3.y, w3, acc.y);
            acc.z = fmaf(v3.z, w3, acc.z); acc.w = fmaf(v3.w, w3, acc.w);
        }
        for (; k < rem; k++) {
            int   s = __shfl_sync(0xffffffffu, ent.x, k);
            float w = __int_as_float(__shfl_sync(0xffffffffu, ent.y, k));
            float4 v = ((const float4*)(h + (size_t)s * 128))[lane];
            acc.x = fmaf(v.x, w, acc.x); acc.y = fmaf(v.y, w, acc.y);
            acc.z = fmaf(v.z, w, acc.z); acc.w = fmaf(v.w, w, acc.w);
        }
    }

    if (LAYER == 0) {
        float4 b = ((const float4*)b1)[lane];
        acc.x = fmaxf(acc.x + b.x, 0.0f);
        acc.y = fmaxf(acc.y + b.y, 0.0f);
        acc.z = fmaxf(acc.z + b.z, 0.0f);
        acc.w = fmaxf(acc.w + b.w, 0.0f);
        ((float4*)(g_h2 + (size_t)n * 128))[lane] = acc;
    } else {
        ((float4*)(g_agg2 + (size_t)n * 128))[lane] = acc;
    }
}

// --------------------------------------------------------------------------------
extern "C" void kernel_launch(void* const* d_in, const int* in_sizes, int n_in,
                              void* d_out, int out_size) {
    const float* x    = (const float*)d_in[0];
    const int*   ei   = (const int*)d_in[1];     // edge_index: int32
    const float* W1   = (const float*)d_in[2];
    const float* b1   = (const float*)d_in[3];
    const float* Wmu  = (const float*)d_in[4];
    const float* bmu  = (const float*)d_in[5];
    const float* Wvar = (const float*)d_in[6];
    const float* bvar = (const float*)d_in[7];

    const int E = in_sizes[1] / 2;
    const int* src = ei;
    const int* dst = ei + E;

    float* outMu  = (float*)d_out;
    float* outSig = (float*)d_out + (size_t)N_NODES * D_DIM;

    const int aggBlocks = (N_NODES * 32 + 255) / 256;   // one warp per node

    // 1-3: CSR counts + scan
    zero_cnt_kernel<<<(N_NODES + 255) / 256, 256>>>();
    count_kernel  <<<(E + 255) / 256, 256>>>(dst, E);
    scan_kernel   <<<1, 1024>>>();

    // 4: layer-1 tf32 GEMM (h1) — ncu capture slot
    tgemm_kernel<0><<<(N_NODES + 127) / 128, 256>>>(x, W1, nullptr, nullptr, N_NODES, F_IN);

    // 5: CSR fill (independent of GEMM)
    fill_kernel<<<(E + 255) / 256, 256>>>(src, dst, E);

    // 6: layer-1 aggregate + fused relu (writes h2)
    aggregate_kernel<0><<<aggBlocks, 256>>>(b1);

    // 7: layer-2 aggregate (agg2)
    aggregate_kernel<1><<<aggBlocks, 256>>>(nullptr);

    // 8: pack fused projection weights
    pack_w_kernel<<<(H_DIM * 128 + 255) / 256, 256>>>(Wmu, Wvar, bmu, bvar);

    // 9: fused mu/sigma tf32 GEMM into d_out
    tgemm_kernel<1><<<(N_NODES + 127) / 128, 256>>>(nullptr, nullptr, outMu, outSig,
                                                    N_NODES, H_DIM);
}